// round 1
// baseline (speedup 1.0000x reference)
#include <cuda_runtime.h>

// Problem constants (fixed by the reference): U=80000, I=40000, N=120000, K=64, L=3, E=1e6
#define KF 64
#define N_MAX 120000

// Scratch (no allocations allowed -> device globals)
__device__ __align__(16) float g_x[(size_t)N_MAX * KF];
__device__ __align__(16) float g_side[(size_t)N_MAX * KF];

// ---------------------------------------------------------------------------
// Kernel 1: e0 = l2norm(concat(Gu, Gi)); zero side; out[n] = rowsum/256
// one warp per node, lane handles 2 features
// ---------------------------------------------------------------------------
__global__ __launch_bounds__(256) void init_kernel(
    const float* __restrict__ Gu, const float* __restrict__ Gi,
    float* __restrict__ out, int U, int Nn)
{
    int w = (blockIdx.x * blockDim.x + threadIdx.x) >> 5;
    if (w >= Nn) return;
    int lane = threadIdx.x & 31;
    const float* src = (w < U) ? (Gu + (size_t)w * KF) : (Gi + (size_t)(w - U) * KF);
    float2 v = ((const float2*)src)[lane];
    float ss = v.x * v.x + v.y * v.y;
    float sm = v.x + v.y;
#pragma unroll
    for (int off = 16; off >= 1; off >>= 1) {
        ss += __shfl_xor_sync(0xffffffffu, ss, off);
        sm += __shfl_xor_sync(0xffffffffu, sm, off);
    }
    float inv = 1.f / fmaxf(sqrtf(ss), 1e-12f);
    float2 o; o.x = v.x * inv; o.y = v.y * inv;
    ((float2*)(g_x + (size_t)w * KF))[lane] = o;
    float2 z; z.x = 0.f; z.y = 0.f;
    ((float2*)(g_side + (size_t)w * KF))[lane] = z;
    if (lane == 0) out[w] = sm * inv * (1.f / 256.f);
}

// ---------------------------------------------------------------------------
// Kernel 2: symmetric SpMM scatter. One warp per undirected edge:
//   lanes 0-15:  side[u] += x[i]   (float4 per lane)
//   lanes 16-31: side[i] += x[u]
// Uses red.global.add.v4.f32 (sm_90+) -> no return trip, 16B per op.
// ---------------------------------------------------------------------------
__global__ __launch_bounds__(256) void scatter_kernel(
    const int* __restrict__ eu, const int* __restrict__ ei, int E)
{
    int idx = blockIdx.x * blockDim.x + threadIdx.x;
    int e = idx >> 5;
    if (e >= E) return;
    int lane = idx & 31;
    int u = __ldg(eu + e);
    int i = __ldg(ei + e);
    int half = lane >> 4;
    int l4 = lane & 15;
    int src = half ? u : i;
    int dst = half ? i : u;
    const float4 v = *(const float4*)(g_x + (size_t)src * KF + (size_t)l4 * 4);
    float* p = g_side + (size_t)dst * KF + (size_t)l4 * 4;
    asm volatile("red.global.add.v4.f32 [%0], {%1, %2, %3, %4};"
                 :: "l"(p), "f"(v.x), "f"(v.y), "f"(v.z), "f"(v.w)
                 : "memory");
}

// ---------------------------------------------------------------------------
// Kernel 3: per-layer dense transform + leaky_relu + l2norm + out accumulation.
// Block = 256 threads, processes 64 nodes. W1,W2 staged in smem (32KB),
// s = side + x and p = side * x staged in padded smem (bank-conflict-free).
// Thread (jt,g): jt in [0,16) owns output features jj=4*jt (float4 of W),
// g in [0,16) owns 4 nodes -> 16 accum registers, W smem loads amortized 4x.
// Also re-zeros g_side rows for the next layer's scatter.
// ---------------------------------------------------------------------------
__device__ __forceinline__ void finish_node(float4 h, int node, int jt, int jj,
                                            float* __restrict__ out)
{
    h.x = h.x > 0.f ? h.x : 0.01f * h.x;
    h.y = h.y > 0.f ? h.y : 0.01f * h.y;
    h.z = h.z > 0.f ? h.z : 0.01f * h.z;
    h.w = h.w > 0.f ? h.w : 0.01f * h.w;
    float ss = h.x * h.x + h.y * h.y + h.z * h.z + h.w * h.w;
    float sm = h.x + h.y + h.z + h.w;
#pragma unroll
    for (int off = 8; off >= 1; off >>= 1) {  // reduce across the 16-lane group
        ss += __shfl_xor_sync(0xffffffffu, ss, off);
        sm += __shfl_xor_sync(0xffffffffu, sm, off);
    }
    float inv = 1.f / fmaxf(sqrtf(ss), 1e-12f);
    h.x *= inv; h.y *= inv; h.z *= inv; h.w *= inv;
    *(float4*)(g_x + (size_t)node * KF + jj) = h;
    if (jt == 0) out[node] += sm * inv * (1.f / 256.f);
}

#define SPITCH 65  // padded row pitch for s/p tiles (kills bank conflicts)
// dynamic smem: W1(4096) + W2(4096) + sS(64*65) + sP(64*65) + sb(64) floats
#define LAYER_SMEM_FLOATS (4096 + 4096 + 64 * SPITCH + 64 * SPITCH + 64)
#define LAYER_SMEM_BYTES (LAYER_SMEM_FLOATS * 4)

__global__ __launch_bounds__(256) void layer_kernel(
    const float* __restrict__ W1, const float* __restrict__ b1,
    const float* __restrict__ W2, const float* __restrict__ b2,
    float* __restrict__ out)
{
    extern __shared__ float smem[];
    float* sW1 = smem;                 // [64][64]
    float* sW2 = smem + 4096;          // [64][64]
    float* sS  = smem + 8192;          // [64][65]
    float* sP  = sS + 64 * SPITCH;     // [64][65]
    float* sb  = sP + 64 * SPITCH;     // [64]

    int t = threadIdx.x;
#pragma unroll
    for (int idx = t; idx < 4096; idx += 256) {
        sW1[idx] = W1[idx];
        sW2[idx] = W2[idx];
    }
    if (t < 64) sb[t] = b1[t] + b2[t];

    int base = blockIdx.x * 64;
    // stage s = side + x, p = side * x; re-zero side for the next scatter
#pragma unroll
    for (int idx = t; idx < 4096; idx += 256) {
        int nn = idx >> 6, k = idx & 63;
        size_t off = (size_t)(base + nn) * KF + k;
        float xv = g_x[off];
        float sv = g_side[off];
        sS[nn * SPITCH + k] = sv + xv;
        sP[nn * SPITCH + k] = sv * xv;
        g_side[off] = 0.f;
    }
    __syncthreads();

    int jt = t & 15;
    int g  = t >> 4;
    int jj = jt * 4;

    float4 bv = *(float4*)(sb + jj);
    float4 a0 = bv, a1 = bv, a2 = bv, a3 = bv;

    const float* s0 = sS + (g * 4 + 0) * SPITCH;
    const float* s1 = sS + (g * 4 + 1) * SPITCH;
    const float* s2 = sS + (g * 4 + 2) * SPITCH;
    const float* s3 = sS + (g * 4 + 3) * SPITCH;
    const float* p0 = sP + (g * 4 + 0) * SPITCH;
    const float* p1 = sP + (g * 4 + 1) * SPITCH;
    const float* p2 = sP + (g * 4 + 2) * SPITCH;
    const float* p3 = sP + (g * 4 + 3) * SPITCH;

#pragma unroll 8
    for (int k = 0; k < 64; ++k) {
        float4 w1 = *(const float4*)(sW1 + k * 64 + jj);
        float4 w2 = *(const float4*)(sW2 + k * 64 + jj);
        float s, p;
        s = s0[k]; p = p0[k];
        a0.x += s * w1.x + p * w2.x;
        a0.y += s * w1.y + p * w2.y;
        a0.z += s * w1.z + p * w2.z;
        a0.w += s * w1.w + p * w2.w;
        s = s1[k]; p = p1[k];
        a1.x += s * w1.x + p * w2.x;
        a1.y += s * w1.y + p * w2.y;
        a1.z += s * w1.z + p * w2.z;
        a1.w += s * w1.w + p * w2.w;
        s = s2[k]; p = p2[k];
        a2.x += s * w1.x + p * w2.x;
        a2.y += s * w1.y + p * w2.y;
        a2.z += s * w1.z + p * w2.z;
        a2.w += s * w1.w + p * w2.w;
        s = s3[k]; p = p3[k];
        a3.x += s * w1.x + p * w2.x;
        a3.y += s * w1.y + p * w2.y;
        a3.z += s * w1.z + p * w2.z;
        a3.w += s * w1.w + p * w2.w;
    }

    int nb = base + g * 4;
    finish_node(a0, nb + 0, jt, jj, out);
    finish_node(a1, nb + 1, jt, jj, out);
    finish_node(a2, nb + 2, jt, jj, out);
    finish_node(a3, nb + 3, jt, jj, out);
}

// ---------------------------------------------------------------------------
// Launch: init -> L x (scatter -> layer). All graph-capturable, no allocs.
// ---------------------------------------------------------------------------
extern "C" void kernel_launch(void* const* d_in, const int* in_sizes, int n_in,
                              void* d_out, int out_size)
{
    const float* Gu = (const float*)d_in[0];
    const float* Gi = (const float*)d_in[1];
    const float* W1 = (const float*)d_in[2];
    const float* b1 = (const float*)d_in[3];
    const float* W2 = (const float*)d_in[4];
    const float* b2 = (const float*)d_in[5];
    const int*   ed = (const int*)d_in[6];
    float* out = (float*)d_out;

    int U  = in_sizes[0] / KF;
    int I  = in_sizes[1] / KF;
    int Nn = U + I;
    int L  = in_sizes[3] / KF;
    int E  = in_sizes[6] / 2;

    cudaFuncSetAttribute(layer_kernel,
                         cudaFuncAttributeMaxDynamicSharedMemorySize,
                         LAYER_SMEM_BYTES);

    int initBlocks = (Nn * 32 + 255) / 256;
    init_kernel<<<initBlocks, 256>>>(Gu, Gi, out, U, Nn);

    long long sthreads = (long long)E * 32;
    int sBlocks = (int)((sthreads + 255) / 256);
    int lBlocks = Nn / 64;  // N = 120000 divisible by 64

    for (int l = 0; l < L; ++l) {
        scatter_kernel<<<sBlocks, 256>>>(ed, ed + E, E);
        layer_kernel<<<lBlocks, 256, LAYER_SMEM_BYTES>>>(
            W1 + (size_t)l * KF * KF, b1 + (size_t)l * KF,
            W2 + (size_t)l * KF * KF, b2 + (size_t)l * KF,
            out);
    }
}

// round 2
// speedup vs baseline: 1.2779x; 1.2779x over previous
#include <cuda_runtime.h>

// Fixed problem shape: U=80000, I=40000, N=120000, K=64, L=3, E=1e6
#define KF 64
#define NN 120000
#define EMAX 1000000
#define FULLMASK 0xffffffffu

// --------------------------- device scratch (no allocs allowed) -------------
__device__ __align__(16) float g_x0[(size_t)NN * KF];
__device__ __align__(16) float g_x1[(size_t)NN * KF];
__device__ int g_deg[NN];
__device__ int g_start[NN + 1];
__device__ int g_cursor[NN];
__device__ int g_bsum[512];
__device__ int g_adj[2 * EMAX];

// =============================================================================
// init: e0 = l2norm(concat(Gu,Gi)) -> g_x0 ; out[n] = rowsum/256 ; deg = 0
// one warp per node, lane owns 2 features
// =============================================================================
__global__ __launch_bounds__(256) void init_kernel(
    const float* __restrict__ Gu, const float* __restrict__ Gi,
    float* __restrict__ out, int U, int Nn)
{
    int w = (blockIdx.x * blockDim.x + threadIdx.x) >> 5;
    if (w >= Nn) return;
    int lane = threadIdx.x & 31;
    const float* src = (w < U) ? (Gu + (size_t)w * KF) : (Gi + (size_t)(w - U) * KF);
    float2 v = ((const float2*)src)[lane];
    float ss = v.x * v.x + v.y * v.y;
    float sm = v.x + v.y;
#pragma unroll
    for (int off = 16; off >= 1; off >>= 1) {
        ss += __shfl_xor_sync(FULLMASK, ss, off);
        sm += __shfl_xor_sync(FULLMASK, sm, off);
    }
    float inv = 1.f / fmaxf(sqrtf(ss), 1e-12f);
    float2 o; o.x = v.x * inv; o.y = v.y * inv;
    ((float2*)(g_x0 + (size_t)w * KF))[lane] = o;
    if (lane == 0) { out[w] = sm * inv * (1.f / 256.f); g_deg[w] = 0; }
}

// =============================================================================
// CSR build: histogram -> 2-level exclusive scan -> bucket fill
// directed edges: idx<E: (src=ei, dst=eu) ; idx>=E: (src=eu, dst=ei)
// =============================================================================
__global__ __launch_bounds__(256) void hist_kernel(
    const int* __restrict__ eu, const int* __restrict__ ei, int E)
{
    int idx = blockIdx.x * blockDim.x + threadIdx.x;
    if (idx >= 2 * E) return;
    int dst = (idx < E) ? eu[idx] : ei[idx - E];
    atomicAdd(&g_deg[dst], 1);
}

__global__ __launch_bounds__(256) void scan1_kernel(int Nn)
{
    int i = blockIdx.x * 256 + threadIdx.x;
    int d = (i < Nn) ? g_deg[i] : 0;
    int lane = threadIdx.x & 31, wid = threadIdx.x >> 5;
    int v = d;
#pragma unroll
    for (int off = 1; off < 32; off <<= 1) {
        int t = __shfl_up_sync(FULLMASK, v, off);
        if (lane >= off) v += t;
    }
    __shared__ int wsum[8];
    if (lane == 31) wsum[wid] = v;
    __syncthreads();
    if (threadIdx.x < 8) {
        int wv = wsum[threadIdx.x];
#pragma unroll
        for (int off = 1; off < 8; off <<= 1) {
            int t = __shfl_up_sync(0xffu, wv, off);
            if ((int)threadIdx.x >= off) wv += t;
        }
        wsum[threadIdx.x] = wv;
    }
    __syncthreads();
    int woff = (wid > 0) ? wsum[wid - 1] : 0;
    if (i < Nn) g_start[i] = woff + v - d;         // per-block exclusive prefix
    if (threadIdx.x == 0) g_bsum[blockIdx.x] = wsum[7];  // block total
}

__global__ __launch_bounds__(512) void scan2_kernel(int nb)
{
    __shared__ int s[512];
    int t = threadIdx.x;
    int v = (t < nb) ? g_bsum[t] : 0;
    s[t] = v;
    __syncthreads();
#pragma unroll
    for (int off = 1; off < 512; off <<= 1) {
        int a = (t >= off) ? s[t - off] : 0;
        __syncthreads();
        s[t] += a;
        __syncthreads();
    }
    if (t < nb) g_bsum[t] = s[t] - v;  // exclusive
}

__global__ __launch_bounds__(256) void scan3_kernel(int Nn, int twoE)
{
    int i = blockIdx.x * 256 + threadIdx.x;
    if (i < Nn) {
        int st = g_start[i] + g_bsum[blockIdx.x];
        g_start[i] = st;
        g_cursor[i] = st;
    }
    if (i == 0) g_start[Nn] = twoE;
}

__global__ __launch_bounds__(256) void fill_kernel(
    const int* __restrict__ eu, const int* __restrict__ ei, int E)
{
    int idx = blockIdx.x * blockDim.x + threadIdx.x;
    if (idx >= 2 * E) return;
    int dst, src;
    if (idx < E) { dst = eu[idx]; src = ei[idx]; }
    else         { dst = ei[idx - E]; src = eu[idx - E]; }
    int pos = atomicAdd(&g_cursor[dst], 1);
    g_adj[pos] = src;
}

// =============================================================================
// Fused layer: CSR gather (side = A@x) -> stage duplicated s/p tiles ->
// packed f32x2 dual-GEMM -> leaky_relu -> l2norm -> write xout, accumulate out.
// Block = 256 threads, 64 nodes.
// =============================================================================
typedef unsigned long long ull;

#define FMA2(d, a, b) asm("fma.rn.f32x2 %0, %1, %2, %0;" : "+l"(d) : "l"(a), "l"(b))

__device__ __forceinline__ ull pack2(float a, float b)
{
    ull r;
    asm("mov.b64 %0, {%1, %2};" : "=l"(r) : "f"(a), "f"(b));
    return r;
}
__device__ __forceinline__ float2 unpack2(ull v)
{
    float2 r;
    asm("mov.b64 {%0, %1}, %2;" : "=f"(r.x), "=f"(r.y) : "l"(v));
    return r;
}

#define PITCH2 132  // floats per duplicated tile row (128 data + 4 pad)
// smem floats: sW1 4096 | sW2 4096 | sS2 64*132 | sP2 64*132 | sb 64
#define SM_W2   4096
#define SM_S2   8192
#define SM_P2   (8192 + 64 * PITCH2)
#define SM_B    (8192 + 2 * 64 * PITCH2)
#define LAYER_SMEM_FLOATS (SM_B + 64)
#define LAYER_SMEM_BYTES  (LAYER_SMEM_FLOATS * 4)

__global__ __launch_bounds__(256, 2) void layer_kernel(
    const float* __restrict__ xin, float* __restrict__ xout,
    const float* __restrict__ W1, const float* __restrict__ b1,
    const float* __restrict__ W2, const float* __restrict__ b2,
    float* __restrict__ out)
{
    extern __shared__ float smem[];
    float* sW1 = smem;
    float* sW2 = smem + SM_W2;
    float* sS2 = smem + SM_S2;
    float* sP2 = smem + SM_P2;
    float* sb  = smem + SM_B;

    int t = threadIdx.x;
#pragma unroll
    for (int idx = t; idx < 4096; idx += 256) {
        sW1[idx] = W1[idx];
        sW2[idx] = W2[idx];
    }
    if (t < 64) sb[t] = b1[t] + b2[t];

    int base = blockIdx.x * 64;
    int w = t >> 5, lane = t & 31;
    const float2* xin2 = (const float2*)xin;

    // ---- gather + stage (warp handles 8 nodes) ----
    for (int j = 0; j < 8; ++j) {
        int nl = w * 8 + j;
        int node = base + nl;
        int a  = g_start[node];
        int e0 = g_start[node + 1];
        float ax = 0.f, ay = 0.f;
        for (; a + 4 <= e0; a += 4) {
            int n0 = __ldg(g_adj + a);
            int n1 = __ldg(g_adj + a + 1);
            int n2 = __ldg(g_adj + a + 2);
            int n3 = __ldg(g_adj + a + 3);
            float2 v0 = __ldg(xin2 + (size_t)n0 * 32 + lane);
            float2 v1 = __ldg(xin2 + (size_t)n1 * 32 + lane);
            float2 v2 = __ldg(xin2 + (size_t)n2 * 32 + lane);
            float2 v3 = __ldg(xin2 + (size_t)n3 * 32 + lane);
            ax += (v0.x + v1.x) + (v2.x + v3.x);
            ay += (v0.y + v1.y) + (v2.y + v3.y);
        }
        int m = e0 - a;
        if (m > 0) { float2 v = __ldg(xin2 + (size_t)__ldg(g_adj + a)     * 32 + lane); ax += v.x; ay += v.y; }
        if (m > 1) { float2 v = __ldg(xin2 + (size_t)__ldg(g_adj + a + 1) * 32 + lane); ax += v.x; ay += v.y; }
        if (m > 2) { float2 v = __ldg(xin2 + (size_t)__ldg(g_adj + a + 2) * 32 + lane); ax += v.x; ay += v.y; }

        float2 xv = __ldg(xin2 + (size_t)node * 32 + lane);
        float sx = ax + xv.x, sy = ay + xv.y;
        float px = ax * xv.x, py = ay * xv.y;
        *(float4*)(sS2 + nl * PITCH2 + lane * 4) = make_float4(sx, sx, sy, sy);
        *(float4*)(sP2 + nl * PITCH2 + lane * 4) = make_float4(px, px, py, py);
    }
    __syncthreads();

    // ---- dual GEMM, packed f32x2 ----
    int jt = t & 15, g = t >> 4;
    int jj = jt * 4;

    float4 bv = *(float4*)(sb + jj);
    ull a00 = pack2(bv.x, bv.y), a01 = pack2(bv.z, bv.w);
    ull a10 = a00, a11 = a01;
    ull a20 = a00, a21 = a01;
    ull a30 = a00, a31 = a01;

    const float* r0s = sS2 + (g * 4 + 0) * PITCH2;
    const float* r1s = sS2 + (g * 4 + 1) * PITCH2;
    const float* r2s = sS2 + (g * 4 + 2) * PITCH2;
    const float* r3s = sS2 + (g * 4 + 3) * PITCH2;
    const float* r0p = sP2 + (g * 4 + 0) * PITCH2;
    const float* r1p = sP2 + (g * 4 + 1) * PITCH2;
    const float* r2p = sP2 + (g * 4 + 2) * PITCH2;
    const float* r3p = sP2 + (g * 4 + 3) * PITCH2;

#pragma unroll 4
    for (int k = 0; k < 64; ++k) {
        ulonglong2 w1p = *(const ulonglong2*)(sW1 + k * 64 + jj);
        ulonglong2 w2p = *(const ulonglong2*)(sW2 + k * 64 + jj);
        ull sv, pv;
        sv = *(const ull*)(r0s + 2 * k); pv = *(const ull*)(r0p + 2 * k);
        FMA2(a00, sv, w1p.x); FMA2(a00, pv, w2p.x);
        FMA2(a01, sv, w1p.y); FMA2(a01, pv, w2p.y);
        sv = *(const ull*)(r1s + 2 * k); pv = *(const ull*)(r1p + 2 * k);
        FMA2(a10, sv, w1p.x); FMA2(a10, pv, w2p.x);
        FMA2(a11, sv, w1p.y); FMA2(a11, pv, w2p.y);
        sv = *(const ull*)(r2s + 2 * k); pv = *(const ull*)(r2p + 2 * k);
        FMA2(a20, sv, w1p.x); FMA2(a20, pv, w2p.x);
        FMA2(a21, sv, w1p.y); FMA2(a21, pv, w2p.y);
        sv = *(const ull*)(r3s + 2 * k); pv = *(const ull*)(r3p + 2 * k);
        FMA2(a30, sv, w1p.x); FMA2(a30, pv, w2p.x);
        FMA2(a31, sv, w1p.y); FMA2(a31, pv, w2p.y);
    }

    // ---- epilogue: leaky_relu + group l2norm + write ----
    ull accs[4][2] = {{a00, a01}, {a10, a11}, {a20, a21}, {a30, a31}};
#pragma unroll
    for (int n = 0; n < 4; ++n) {
        float2 lo = unpack2(accs[n][0]);
        float2 hi = unpack2(accs[n][1]);
        float4 h = make_float4(lo.x, lo.y, hi.x, hi.y);
        h.x = h.x > 0.f ? h.x : 0.01f * h.x;
        h.y = h.y > 0.f ? h.y : 0.01f * h.y;
        h.z = h.z > 0.f ? h.z : 0.01f * h.z;
        h.w = h.w > 0.f ? h.w : 0.01f * h.w;
        float ss = h.x * h.x + h.y * h.y + h.z * h.z + h.w * h.w;
        float sm = h.x + h.y + h.z + h.w;
#pragma unroll
        for (int off = 8; off >= 1; off >>= 1) {
            ss += __shfl_xor_sync(FULLMASK, ss, off);
            sm += __shfl_xor_sync(FULLMASK, sm, off);
        }
        float inv = 1.f / fmaxf(sqrtf(ss), 1e-12f);
        h.x *= inv; h.y *= inv; h.z *= inv; h.w *= inv;
        int node = base + g * 4 + n;
        *(float4*)(xout + (size_t)node * KF + jj) = h;
        if (jt == 0) out[node] += sm * inv * (1.f / 256.f);
    }
}

// =============================================================================
// launch: init -> CSR build -> 3 x fused layer (ping-pong x buffers)
// =============================================================================
extern "C" void kernel_launch(void* const* d_in, const int* in_sizes, int n_in,
                              void* d_out, int out_size)
{
    const float* Gu = (const float*)d_in[0];
    const float* Gi = (const float*)d_in[1];
    const float* W1 = (const float*)d_in[2];
    const float* b1 = (const float*)d_in[3];
    const float* W2 = (const float*)d_in[4];
    const float* b2 = (const float*)d_in[5];
    const int*   ed = (const int*)d_in[6];
    float* out = (float*)d_out;

    int U  = in_sizes[0] / KF;
    int I  = in_sizes[1] / KF;
    int Nn = U + I;
    int L  = in_sizes[3] / KF;
    int E  = in_sizes[6] / 2;
    int twoE = 2 * E;

    const int* eu = ed;
    const int* ei = ed + E;

    static int smem_set = 0;
    cudaFuncSetAttribute(layer_kernel,
                         cudaFuncAttributeMaxDynamicSharedMemorySize,
                         LAYER_SMEM_BYTES);
    (void)smem_set;

    float *xa, *xb;
    cudaGetSymbolAddress((void**)&xa, g_x0);
    cudaGetSymbolAddress((void**)&xb, g_x1);

    int initBlocks = (Nn * 32 + 255) / 256;
    init_kernel<<<initBlocks, 256>>>(Gu, Gi, out, U, Nn);

    int eBlocks = (twoE + 255) / 256;
    int nBlocks = (Nn + 255) / 256;
    hist_kernel<<<eBlocks, 256>>>(eu, ei, E);
    scan1_kernel<<<nBlocks, 256>>>(Nn);
    scan2_kernel<<<1, 512>>>(nBlocks);
    scan3_kernel<<<nBlocks, 256>>>(Nn, twoE);
    fill_kernel<<<eBlocks, 256>>>(eu, ei, E);

    int lBlocks = Nn / 64;  // 120000 / 64 = 1875
    for (int l = 0; l < L; ++l) {
        layer_kernel<<<lBlocks, 256, LAYER_SMEM_BYTES>>>(
            xa, xb,
            W1 + (size_t)l * KF * KF, b1 + (size_t)l * KF,
            W2 + (size_t)l * KF * KF, b2 + (size_t)l * KF,
            out);
        float* tmp = xa; xa = xb; xb = tmp;
    }
}